// round 9
// baseline (speedup 1.0000x reference)
#include <cuda_runtime.h>
#include <cstdint>
#include <cstddef>

// ---------------- problem dims ----------------
#define A_DIM 4
#define M_DIM 1024
#define H_DIM 1024
#define E_DIM 8
#define N_DIM 4096
#define SPLITK_C 4     /* split-K factor for the combine GEMM */

// ---------------- tile config ----------------
#define BM 128
#define BN 128
#define BK 32
#define NSTAGE 5
#define NTHREADS 128   /* 4 warps, warp tile 64x64 */
// padded smem strides (floats) for conflict-free fragment LDS
#define LDA_S 36     /* A tile row stride: bank=(4g+q)%32 distinct */
#define LDB_S 136    /* B tile row stride: bank=(8q+g)%32 distinct */
#define A_STG_FLOATS (BM * LDA_S)          /* 4608 */
#define B_STG_FLOATS (BK * LDB_S)          /* 4352 */
#define STG_FLOATS   (A_STG_FLOATS + B_STG_FLOATS)   /* 8960 = 35840 B */
#define SMEM_DYN     (NSTAGE * STG_FLOATS * 4)       /* 179200 B -> 1 CTA/SM */

// ---------------- device scratch ----------------
__device__ float g_part[(size_t)E_DIM * SPLITK_C * H_DIM * H_DIM]; // 128 MB partials
__device__ float g_wsum[(size_t)H_DIM * H_DIM];                    // 4 MB combined W

// ---------------- helpers ----------------
__device__ __forceinline__ uint32_t smem_u32(const void* p) {
    uint32_t a;
    asm("{ .reg .u64 t; cvta.to.shared.u64 t, %1; cvt.u32.u64 %0, t; }" : "=r"(a) : "l"(p));
    return a;
}
__device__ __forceinline__ float rna_tf32(float f) {
    asm("cvt.rna.tf32.f32 %0, %0;" : "+f"(f));
    return f;
}
__device__ __forceinline__ uint32_t rna_tf32_u(uint32_t u) {
    asm("cvt.rna.tf32.f32 %0, %0;" : "+r"(u));
    return u;
}
__device__ __forceinline__ void cp16(uint32_t dst, const float* src) {
    asm volatile("cp.async.cg.shared.global [%0], [%1], 16;\n"
                 :: "r"(dst), "l"(__cvta_generic_to_global(src)) : "memory");
}
__device__ __forceinline__ void cp_commit() {
    asm volatile("cp.async.commit_group;\n" ::: "memory");
}
__device__ __forceinline__ void mma_tf32(float* c, const uint32_t* a, const uint32_t* b) {
    asm volatile(
        "mma.sync.aligned.m16n8k8.row.col.f32.tf32.tf32.f32 "
        "{%0,%1,%2,%3}, {%4,%5,%6,%7}, {%8,%9}, {%0,%1,%2,%3};"
        : "+f"(c[0]), "+f"(c[1]), "+f"(c[2]), "+f"(c[3])
        : "r"(a[0]), "r"(a[1]), "r"(a[2]), "r"(a[3]), "r"(b[0]), "r"(b[1]));
}

// =============================================================================
// tf32 GEMM: split-K batching, cross-iteration fragment pipeline, 1 CTA/SM,
// deep (NSTAGE=5) cp.async pipeline with constant group-count discipline.
// =============================================================================
template <int KB, int SPLITK, bool RND_A, bool RND_B>
__global__ void __launch_bounds__(NTHREADS, 1)
gemm_tf32_ker(const float* __restrict__ Ag, const float* __restrict__ Bg,
              float* __restrict__ Cg,
              int lda, int ldb, int ldc,
              size_t a_batch_stride, size_t b_batch_stride, size_t c_batch_stride) {
    extern __shared__ float sm[];

    const int tid  = threadIdx.x;
    const int lane = tid & 31;
    const int warp = tid >> 5;
    const int g = lane >> 2;          // 0..7
    const int q = lane & 3;           // 0..3
    const int wm = warp & 1;          // warp m index (2)
    const int wn = warp >> 1;         // warp n index (2)

    const int bz = blockIdx.z;
    const int zo = bz / SPLITK;
    const int ks_slice = bz % SPLITK;

    const float* A = Ag + (size_t)zo * a_batch_stride
                        + (size_t)ks_slice * KB * BK
                        + (size_t)blockIdx.y * BM * lda;
    const float* B = Bg + (size_t)zo * b_batch_stride
                        + (size_t)ks_slice * KB * BK * ldb
                        + (size_t)blockIdx.x * BN;
    float*       C = Cg + (size_t)bz * c_batch_stride
                        + (size_t)blockIdx.y * BM * ldc + (size_t)blockIdx.x * BN;

    const uint32_t smem0 = smem_u32(sm);

    // ---- gmem -> smem geometry (16B chunks, 128 threads: 8 A + 8 B chunks each) ----
    const int ar = tid >> 3;            // A base row (0..15), +16*i
    const int ac = (tid & 7) * 4;       // A float col
    const int br = tid >> 5;            // B base row (0..3), +4*i
    const int bc = (tid & 31) * 4;      // B float col

    auto load_stage = [&](int slot, int kb) {
        uint32_t sa = smem0 + (uint32_t)slot * (STG_FLOATS * 4);
        uint32_t sb = sa + A_STG_FLOATS * 4;
        const float* Ak = A + (size_t)kb * BK;
        const float* Bk = B + (size_t)kb * BK * ldb;
        #pragma unroll
        for (int i = 0; i < 8; i++) {
            int r = ar + 16 * i;
            cp16(sa + (uint32_t)(r * LDA_S + ac) * 4u, Ak + (size_t)r * lda + ac);
        }
        #pragma unroll
        for (int i = 0; i < 8; i++) {
            int r = br + 4 * i;
            cp16(sb + (uint32_t)(r * LDB_S + bc) * 4u, Bk + (size_t)r * ldb + bc);
        }
        cp_commit();
    };

    // ---- accumulators: 4 m-tiles x 8 n-tiles x 4 ----
    float c[4][8][4];
    #pragma unroll
    for (int mt = 0; mt < 4; mt++)
        #pragma unroll
        for (int nt = 0; nt < 8; nt++)
            #pragma unroll
            for (int i = 0; i < 4; i++) c[mt][nt][i] = 0.0f;

    // fragment double buffers
    uint32_t afr[2][4][4];
    uint32_t bfr[2][8][2];

    auto load_frags = [&](const uint32_t* As, const uint32_t* Bs, int ks, int buf) {
        #pragma unroll
        for (int mt = 0; mt < 4; mt++) {
            int r0 = wm * 64 + mt * 16 + g;
            int c0 = ks * 8 + q;
            uint32_t v0 = As[r0 * LDA_S + c0];
            uint32_t v1 = As[(r0 + 8) * LDA_S + c0];
            uint32_t v2 = As[r0 * LDA_S + c0 + 4];
            uint32_t v3 = As[(r0 + 8) * LDA_S + c0 + 4];
            if (RND_A) { v0 = rna_tf32_u(v0); v1 = rna_tf32_u(v1);
                         v2 = rna_tf32_u(v2); v3 = rna_tf32_u(v3); }
            afr[buf][mt][0] = v0; afr[buf][mt][1] = v1;
            afr[buf][mt][2] = v2; afr[buf][mt][3] = v3;
        }
        #pragma unroll
        for (int nt = 0; nt < 8; nt++) {
            int col = wn * 64 + nt * 8 + g;
            int r0 = ks * 8 + q;
            uint32_t v0 = Bs[r0 * LDB_S + col];
            uint32_t v1 = Bs[(r0 + 4) * LDB_S + col];
            if (RND_B) { v0 = rna_tf32_u(v0); v1 = rna_tf32_u(v1); }
            bfr[buf][nt][0] = v0; bfr[buf][nt][1] = v1;
        }
    };

    auto mma_batch = [&](int buf) {
        #pragma unroll
        for (int mt = 0; mt < 4; mt++)
            #pragma unroll
            for (int nt = 0; nt < 8; nt++)
                mma_tf32(c[mt][nt], afr[buf][mt], bfr[buf][nt]);
    };

    // ---- prologue: NSTAGE-1 stages in flight; frags(kb=0, ks=0) resident ----
    #pragma unroll
    for (int s = 0; s < NSTAGE - 1; s++) {
        if (s < KB) load_stage(s, s);
        else        cp_commit();              // keep group count uniform
    }
    asm volatile("cp.async.wait_group %0;\n" :: "n"(NSTAGE - 2) : "memory"); // stage 0 done
    __syncthreads();
    {
        const uint32_t* As0 = reinterpret_cast<const uint32_t*>(sm);
        load_frags(As0, As0 + A_STG_FLOATS, 0, 0);
    }

    int slot_c = 0, slot_p = NSTAGE - 1;

    // ---- main loop: stage maintenance at the ks2/ks3 seam ----
    #pragma unroll 1
    for (int kb = 0; kb < KB; ++kb) {
        const uint32_t* As = reinterpret_cast<const uint32_t*>(sm + slot_c * STG_FLOATS);
        const uint32_t* Bs = As + A_STG_FLOATS;

        load_frags(As, Bs, 1, 1);
        mma_batch(0);
        load_frags(As, Bs, 2, 0);
        mma_batch(1);
        load_frags(As, Bs, 3, 1);
        mma_batch(0);

        // seam: oldest outstanding group = stage kb+1 -> wait until <= NSTAGE-3 remain
        asm volatile("cp.async.wait_group %0;\n" :: "n"(NSTAGE - 3) : "memory");
        __syncthreads();                                      // stage kb+1 visible
        int pf = kb + NSTAGE - 1;
        if (pf < KB) load_stage(slot_p, pf);
        else         cp_commit();                             // empty group keeps count
        if (++slot_p == NSTAGE) slot_p = 0;

        int slot_n = (slot_c + 1 == NSTAGE) ? 0 : slot_c + 1;
        if (kb + 1 < KB) {
            const uint32_t* An = reinterpret_cast<const uint32_t*>(sm + slot_n * STG_FLOATS);
            load_frags(An, An + A_STG_FLOATS, 0, 0);          // next kb ks0 prefetch
        }
        mma_batch(1);
        slot_c = slot_n;
    }

    // ---- epilogue ----
    #pragma unroll
    for (int mt = 0; mt < 4; mt++) {
        #pragma unroll
        for (int nt = 0; nt < 8; nt++) {
            int r0  = wm * 64 + mt * 16 + g;
            int col = wn * 64 + nt * 8 + 2 * q;
            float2 v0 = make_float2(c[mt][nt][0], c[mt][nt][1]);
            float2 v1 = make_float2(c[mt][nt][2], c[mt][nt][3]);
            *reinterpret_cast<float2*>(C + (size_t)r0 * ldc + col)       = v0;
            *reinterpret_cast<float2*>(C + (size_t)(r0 + 8) * ldc + col) = v1;
        }
    }
}

// ---- reduce E*SPLITK partials into g_wsum, rounding the sum to tf32 ----
__global__ void reduce_experts_ker() {
    size_t i = (size_t)blockIdx.x * blockDim.x + threadIdx.x;  // float4 index
    const float4* p = reinterpret_cast<const float4*>(g_part);
    float4 acc = p[i];
    #pragma unroll
    for (int e = 1; e < E_DIM * SPLITK_C; e++) {
        float4 v = p[(size_t)e * (H_DIM * H_DIM / 4) + i];
        acc.x += v.x; acc.y += v.y; acc.z += v.z; acc.w += v.w;
    }
    acc.x = rna_tf32(acc.x); acc.y = rna_tf32(acc.y);
    acc.z = rna_tf32(acc.z); acc.w = rna_tf32(acc.w);
    reinterpret_cast<float4*>(g_wsum)[i] = acc;
}

// ================= launch =================
extern "C" void kernel_launch(void* const* d_in, const int* in_sizes, int n_in,
                              void* d_out, int out_size) {
    const float* x  = (const float*)d_in[0];
    const float* w1 = (const float*)d_in[1];   // [E][H][N]
    const float* w2 = (const float*)d_in[2];   // [E][N][H]
    float* out = (float*)d_out;                // [A][M][H]

    float* part = nullptr; cudaGetSymbolAddress((void**)&part, g_part);
    float* wsum = nullptr; cudaGetSymbolAddress((void**)&wsum, g_wsum);

    constexpr int KB_C = (N_DIM / BK) / SPLITK_C;   // 32 kb-iters per combine CTA
    constexpr int KB_A = H_DIM / BK;                // 32 kb-iters for apply

    cudaFuncSetAttribute((const void*)gemm_tf32_ker<KB_C, SPLITK_C, true, true>,
                         cudaFuncAttributeMaxDynamicSharedMemorySize, SMEM_DYN);
    cudaFuncSetAttribute((const void*)gemm_tf32_ker<KB_A, 1, true, false>,
                         cudaFuncAttributeMaxDynamicSharedMemorySize, SMEM_DYN);

    // 1) per-expert, split-K combine: g_part[e][s] = rna(w1[e])_Ks @ rna(w2[e])_Ks
    gemm_tf32_ker<KB_C, SPLITK_C, true, true>
        <<<dim3(H_DIM / BN, H_DIM / BM, E_DIM * SPLITK_C), NTHREADS, SMEM_DYN>>>(
            w1, w2, part,
            N_DIM, H_DIM, H_DIM,
            (size_t)H_DIM * N_DIM, (size_t)N_DIM * H_DIM, (size_t)H_DIM * H_DIM);

    // 2) reduce E*SPLITK partials (+ tf32 rounding of the sum)
    reduce_experts_ker<<<(H_DIM * H_DIM / 4) / 256, 256>>>();

    // 3) apply: out = rna(x) @ W   (W pre-rounded by reduce)
    gemm_tf32_ker<KB_A, 1, true, false>
        <<<dim3(H_DIM / BN, (A_DIM * M_DIM) / BM, 1), NTHREADS, SMEM_DYN>>>(
            x, wsum, out,
            H_DIM, H_DIM, H_DIM,
            0, 0, 0);
}

// round 10
// speedup vs baseline: 2.3479x; 2.3479x over previous
#include <cuda_runtime.h>
#include <cuda_fp16.h>
#include <cstdint>
#include <cstddef>

// ---------------- problem dims ----------------
#define A_DIM 4
#define M_DIM 1024
#define H_DIM 1024
#define E_DIM 8
#define N_DIM 4096
#define SPLITK_C 4     /* split-K factor for the combine GEMM */

// ---------------- tile config (word = 2 fp16 along K) ----------------
#define BM 128
#define BN 128
#define BKW 32          /* K-words per kb-iter = 64 halves */
#define NSTAGE 3
#define NTHREADS 128    /* 4 warps, warp tile 64x64 */
#define LDA_W 36        /* A stage row stride (words): bank=(4g+q)%32 distinct */
#define LDB_W 136       /* B stage row stride (words): bank=(8q+g)%32 distinct */
#define A_STG_WORDS (BM * LDA_W)        /* 4608 */
#define B_STG_WORDS (BKW * LDB_W)       /* 4352 */
#define STG_WORDS   (A_STG_WORDS + B_STG_WORDS)   /* 8960 = 35840 B */
#define SMEM_DYN    (NSTAGE * STG_WORDS * 4)      /* 107520 B -> 2 CTA/SM */

// ---------------- device scratch ----------------
__device__ uint32_t g_w1h[(size_t)E_DIM * H_DIM * (N_DIM / 2)];   // 67 MB  w1 fp16 straight
__device__ uint32_t g_w2p[(size_t)E_DIM * (N_DIM / 2) * H_DIM];   // 67 MB  w2 fp16 k-packed
__device__ uint32_t g_xh [(size_t)A_DIM * M_DIM * (H_DIM / 2)];   // 8.4 MB x fp16 straight
__device__ float    g_part[(size_t)E_DIM * SPLITK_C * H_DIM * H_DIM]; // 128 MB fp32 partials
__device__ uint32_t g_wsp[(size_t)(H_DIM / 2) * H_DIM];           // 2 MB   wsum fp16 k-packed

// ---------------- helpers ----------------
__device__ __forceinline__ uint32_t smem_u32(const void* p) {
    uint32_t a;
    asm("{ .reg .u64 t; cvta.to.shared.u64 t, %1; cvt.u32.u64 %0, t; }" : "=r"(a) : "l"(p));
    return a;
}
__device__ __forceinline__ uint32_t pack_h2(float lo, float hi) {
    __half2 h = __float22half2_rn(make_float2(lo, hi));   // .x -> low half
    return *reinterpret_cast<uint32_t*>(&h);
}
__device__ __forceinline__ void cp16(uint32_t dst, const uint32_t* src) {
    asm volatile("cp.async.cg.shared.global [%0], [%1], 16;\n"
                 :: "r"(dst), "l"(__cvta_generic_to_global(src)) : "memory");
}
__device__ __forceinline__ void cp_commit() {
    asm volatile("cp.async.commit_group;\n" ::: "memory");
}
__device__ __forceinline__ void mma_f16(float* c, const uint32_t* a, const uint32_t* b) {
    asm volatile(
        "mma.sync.aligned.m16n8k16.row.col.f32.f16.f16.f32 "
        "{%0,%1,%2,%3}, {%4,%5,%6,%7}, {%8,%9}, {%0,%1,%2,%3};"
        : "+f"(c[0]), "+f"(c[1]), "+f"(c[2]), "+f"(c[3])
        : "r"(a[0]), "r"(a[1]), "r"(a[2]), "r"(a[3]), "r"(b[0]), "r"(b[1]));
}

// ---- prep: fp32 -> fp16 straight (pairs along last dim stay adjacent) ----
__global__ void conv_h_ker(const float* __restrict__ src, uint32_t* __restrict__ dst) {
    size_t i = (size_t)blockIdx.x * blockDim.x + threadIdx.x;   // float4 index
    float4 v = reinterpret_cast<const float4*>(src)[i];
    uint2 o;
    o.x = pack_h2(v.x, v.y);
    o.y = pack_h2(v.z, v.w);
    reinterpret_cast<uint2*>(dst)[i] = o;
}

// ---- prep: w2 [E][N][H] fp32 -> k-packed fp16 words [E][N/2][H] ----
// word(e,kk,n) = (lo = w2[e][2kk][n], hi = w2[e][2kk+1][n])
__global__ void conv_w2p_ker(const float* __restrict__ w2) {
    size_t idx = (size_t)blockIdx.x * blockDim.x + threadIdx.x;  // E*2048*256
    int n4 = (int)(idx & 255);
    int kk = (int)((idx >> 8) & 2047);
    int e  = (int)(idx >> 19);
    const float* base = w2 + ((size_t)e * N_DIM + 2 * kk) * H_DIM + n4 * 4;
    float4 r0 = *reinterpret_cast<const float4*>(base);
    float4 r1 = *reinterpret_cast<const float4*>(base + H_DIM);
    uint4 o;
    o.x = pack_h2(r0.x, r1.x);
    o.y = pack_h2(r0.y, r1.y);
    o.z = pack_h2(r0.z, r1.z);
    o.w = pack_h2(r0.w, r1.w);
    reinterpret_cast<uint4*>(g_w2p)[idx] = o;
}

// =============================================================================
// fp16 GEMM (word-level port of the validated tf32 kernel):
// C[BM x BN](fp32) = A[M x K] * B[K x N], A straight fp16 words, B k-packed.
// 2 CTA/SM, NSTAGE=3, cross-kb fragment pipeline (R7 structure).
// =============================================================================
template <int KB, int SPLITK>
__global__ void __launch_bounds__(NTHREADS, 2)
gemm_f16_ker(const uint32_t* __restrict__ Ag, const uint32_t* __restrict__ Bg,
             float* __restrict__ Cg,
             int lda_w, int ldb_w, int ldc,
             size_t a_batch, size_t b_batch, size_t c_batch) {
    extern __shared__ uint32_t sm[];

    const int tid  = threadIdx.x;
    const int lane = tid & 31;
    const int warp = tid >> 5;
    const int g = lane >> 2;          // 0..7
    const int q = lane & 3;           // 0..3
    const int wm = warp & 1;          // warp m index (2)
    const int wn = warp >> 1;         // warp n index (2)

    const int bz = blockIdx.z;
    const int zo = bz / SPLITK;
    const int sk = bz % SPLITK;

    const uint32_t* A = Ag + (size_t)zo * a_batch + (size_t)sk * KB * BKW
                           + (size_t)blockIdx.y * BM * lda_w;
    const uint32_t* B = Bg + (size_t)zo * b_batch + (size_t)sk * KB * BKW * ldb_w
                           + (size_t)blockIdx.x * BN;
    float*          C = Cg + (size_t)bz * c_batch
                           + (size_t)blockIdx.y * BM * ldc + (size_t)blockIdx.x * BN;

    const uint32_t smem0 = smem_u32(sm);

    // gmem->smem geometry (16B chunks = 4 words)
    const int ar = tid >> 3;            // A base row (0..15), +16*i ; 8 chunks/row
    const int ac = (tid & 7) * 4;       // A word col
    const int br = tid >> 5;            // B base kk-row (0..3), +4*i
    const int bc = (tid & 31) * 4;      // B word col

    auto load_stage = [&](int slot, int kb) {
        uint32_t sa = smem0 + (uint32_t)slot * (STG_WORDS * 4);
        uint32_t sb = sa + A_STG_WORDS * 4;
        const uint32_t* Ak = A + (size_t)kb * BKW;
        const uint32_t* Bk = B + (size_t)kb * BKW * ldb_w;
        #pragma unroll
        for (int i = 0; i < 8; i++) {
            int r = ar + 16 * i;
            cp16(sa + (uint32_t)(r * LDA_W + ac) * 4u, Ak + (size_t)r * lda_w + ac);
        }
        #pragma unroll
        for (int i = 0; i < 8; i++) {
            int r = br + 4 * i;
            cp16(sb + (uint32_t)(r * LDB_W + bc) * 4u, Bk + (size_t)r * ldb_w + bc);
        }
        cp_commit();
    };

    // accumulators: 4 m-tiles x 8 n-tiles x 4 fp32
    float c[4][8][4];
    #pragma unroll
    for (int mt = 0; mt < 4; mt++)
        #pragma unroll
        for (int nt = 0; nt < 8; nt++)
            #pragma unroll
            for (int i = 0; i < 4; i++) c[mt][nt][i] = 0.0f;

    // fragment double buffers
    uint32_t afr[2][4][4];
    uint32_t bfr[2][8][2];

    // ks covers K=16 halves = 8 words; word cols {ks*8+q, ks*8+q+4}
    auto load_frags = [&](const uint32_t* As, const uint32_t* Bs, int ks, int buf) {
        #pragma unroll
        for (int mt = 0; mt < 4; mt++) {
            int r0 = wm * 64 + mt * 16 + g;
            int c0 = ks * 8 + q;
            afr[buf][mt][0] = As[r0 * LDA_W + c0];            // rows g,   k 2q..2q+1
            afr[buf][mt][1] = As[(r0 + 8) * LDA_W + c0];      // rows g+8
            afr[buf][mt][2] = As[r0 * LDA_W + c0 + 4];        // rows g,   k +8
            afr[buf][mt][3] = As[(r0 + 8) * LDA_W + c0 + 4];  // rows g+8, k +8
        }
        #pragma unroll
        for (int nt = 0; nt < 8; nt++) {
            int col = wn * 64 + nt * 8 + g;
            int r0 = ks * 8 + q;
            bfr[buf][nt][0] = Bs[r0 * LDB_W + col];           // kk=q   -> k 2q,2q+1
            bfr[buf][nt][1] = Bs[(r0 + 4) * LDB_W + col];     // kk=q+4 -> k 2q+8,2q+9
        }
    };

    auto mma_batch = [&](int buf) {
        #pragma unroll
        for (int mt = 0; mt < 4; mt++)
            #pragma unroll
            for (int nt = 0; nt < 8; nt++)
                mma_f16(c[mt][nt], afr[buf][mt], bfr[buf][nt]);
    };

    // ---- prologue: stages 0,1 in flight; frags(kb=0, ks=0) resident ----
    load_stage(0, 0);
    load_stage(1, 1);
    asm volatile("cp.async.wait_group 1;\n" ::: "memory");   // stage 0 done
    __syncthreads();
    load_frags(sm, sm + A_STG_WORDS, 0, 0);

    int slot_c = 0, slot_p = 2;

    // ---- main loop: stage maintenance at the ks2/ks3 seam (R7 structure) ----
    #pragma unroll 1
    for (int kb = 0; kb < KB; ++kb) {
        const uint32_t* As = sm + slot_c * STG_WORDS;
        const uint32_t* Bs = As + A_STG_WORDS;

        load_frags(As, Bs, 1, 1);
        mma_batch(0);
        load_frags(As, Bs, 2, 0);
        mma_batch(1);
        load_frags(As, Bs, 3, 1);
        mma_batch(0);

        asm volatile("cp.async.wait_group 0;\n" ::: "memory");  // stage kb+1 landed
        __syncthreads();
        int pf = kb + NSTAGE - 1;
        if (pf < KB) load_stage(slot_p, pf);
        if (++slot_p == NSTAGE) slot_p = 0;

        int slot_n = (slot_c + 1 == NSTAGE) ? 0 : slot_c + 1;
        if (kb + 1 < KB) {
            const uint32_t* An = sm + slot_n * STG_WORDS;
            load_frags(An, An + A_STG_WORDS, 0, 0);
        }
        mma_batch(1);
        slot_c = slot_n;
    }

    // ---- epilogue (fp32 stores) ----
    #pragma unroll
    for (int mt = 0; mt < 4; mt++) {
        #pragma unroll
        for (int nt = 0; nt < 8; nt++) {
            int r0  = wm * 64 + mt * 16 + g;
            int col = wn * 64 + nt * 8 + 2 * q;
            float2 v0 = make_float2(c[mt][nt][0], c[mt][nt][1]);
            float2 v1 = make_float2(c[mt][nt][2], c[mt][nt][3]);
            *reinterpret_cast<float2*>(C + (size_t)r0 * ldc + col)       = v0;
            *reinterpret_cast<float2*>(C + (size_t)(r0 + 8) * ldc + col) = v1;
        }
    }
}

// ---- reduce 32 fp32 partials -> packed fp16 wsum words [kk][n] ----
__global__ void reduce_experts_ker() {
    int idx = blockIdx.x * blockDim.x + threadIdx.x;   // 512 kk x 256 n4
    int n4 = idx & 255;
    int kk = idx >> 8;
    const float4* p = reinterpret_cast<const float4*>(g_part);
    float4 a0 = make_float4(0.f, 0.f, 0.f, 0.f), a1 = a0;
    #pragma unroll
    for (int e = 0; e < E_DIM * SPLITK_C; e++) {
        size_t pl = (size_t)e * (H_DIM * H_DIM / 4);
        float4 v0 = p[pl + (size_t)(2 * kk)     * (H_DIM / 4) + n4];
        float4 v1 = p[pl + (size_t)(2 * kk + 1) * (H_DIM / 4) + n4];
        a0.x += v0.x; a0.y += v0.y; a0.z += v0.z; a0.w += v0.w;
        a1.x += v1.x; a1.y += v1.y; a1.z += v1.z; a1.w += v1.w;
    }
    uint4 o;
    o.x = pack_h2(a0.x, a1.x);
    o.y = pack_h2(a0.y, a1.y);
    o.z = pack_h2(a0.z, a1.z);
    o.w = pack_h2(a0.w, a1.w);
    reinterpret_cast<uint4*>(g_wsp)[idx] = o;
}

// ================= launch =================
extern "C" void kernel_launch(void* const* d_in, const int* in_sizes, int n_in,
                              void* d_out, int out_size) {
    const float* x  = (const float*)d_in[0];
    const float* w1 = (const float*)d_in[1];   // [E][H][N]
    const float* w2 = (const float*)d_in[2];   // [E][N][H]
    float* out = (float*)d_out;                // [A][M][H]

    uint32_t* w1h = nullptr; cudaGetSymbolAddress((void**)&w1h, g_w1h);
    uint32_t* w2p = nullptr; cudaGetSymbolAddress((void**)&w2p, g_w2p);
    uint32_t* xh  = nullptr; cudaGetSymbolAddress((void**)&xh,  g_xh);
    float*    part = nullptr; cudaGetSymbolAddress((void**)&part, g_part);
    uint32_t* wsp = nullptr; cudaGetSymbolAddress((void**)&wsp, g_wsp);

    constexpr int KB_C = (N_DIM / 2 / BKW) / SPLITK_C;  // 16 kb per combine CTA
    constexpr int KB_A = (H_DIM / 2) / BKW;             // 16 kb for apply

    cudaFuncSetAttribute((const void*)gemm_f16_ker<KB_C, SPLITK_C>,
                         cudaFuncAttributeMaxDynamicSharedMemorySize, SMEM_DYN);
    cudaFuncSetAttribute((const void*)gemm_f16_ker<KB_A, 1>,
                         cudaFuncAttributeMaxDynamicSharedMemorySize, SMEM_DYN);

    // 0) fp16 conversions
    conv_h_ker<<<(int)(((size_t)E_DIM * H_DIM * N_DIM / 4) / 256), 256>>>(w1, w1h);
    conv_w2p_ker<<<(int)(((size_t)E_DIM * (N_DIM / 2) * (H_DIM / 4)) / 256), 256>>>(w2);
    conv_h_ker<<<(A_DIM * M_DIM * H_DIM / 4) / 256, 256>>>(x, xh);

    // 1) per-expert split-K combine: g_part[e*4+s] = w1h[e]_Ks @ w2p[e]_Ks
    gemm_f16_ker<KB_C, SPLITK_C>
        <<<dim3(H_DIM / BN, H_DIM / BM, E_DIM * SPLITK_C), NTHREADS, SMEM_DYN>>>(
            w1h, w2p, part,
            N_DIM / 2, H_DIM, H_DIM,
            (size_t)H_DIM * (N_DIM / 2), (size_t)(N_DIM / 2) * H_DIM,
            (size_t)H_DIM * H_DIM);

    // 2) reduce partials -> packed fp16 wsum
    reduce_experts_ker<<<(H_DIM / 2) * (H_DIM / 4) / 256, 256>>>();

    // 3) apply: out = xh @ wsum
    gemm_f16_ker<KB_A, 1>
        <<<dim3(H_DIM / BN, (A_DIM * M_DIM) / BM, 1), NTHREADS, SMEM_DYN>>>(
            xh, wsp, out,
            H_DIM / 2, H_DIM, H_DIM,
            0, 0, 0);
}

// round 11
// speedup vs baseline: 2.3910x; 1.0184x over previous
#include <cuda_runtime.h>
#include <cuda_fp16.h>
#include <cstdint>
#include <cstddef>

// ---------------- problem dims ----------------
#define A_DIM 4
#define M_DIM 1024
#define H_DIM 1024
#define E_DIM 8
#define N_DIM 4096
#define SPLITK_C 4

// ---------------- tile config ----------------
#define BM 128
#define BN 128
#define BKH 64          /* K-halves per kb-iter */
#define NSTAGE 3
#define NTHREADS 128    /* 4 warps, warp tile 64x64 */
#define LDA_W 36        /* A stage row stride in words (2 halves each) */
#define LDB_H 136       /* B stage row stride in halves */
#define A_STG_WORDS (BM * LDA_W)            /* 4608 words = 18432 B */
#define B_STG_WORDS (BKH * LDB_H / 2)       /* 4352 words = 17408 B */
#define STG_WORDS   (A_STG_WORDS + B_STG_WORDS)   /* 8960 = 35840 B */
#define STG_BYTES   (STG_WORDS * 4)
#define SMEM_DYN    (NSTAGE * STG_BYTES)          /* 107520 B -> 2 CTA/SM */

// ---------------- device scratch ----------------
__device__ uint32_t g_w1h[(size_t)E_DIM * H_DIM * (N_DIM / 2)];   // w1 fp16 (words)
__device__ __half   g_w2h[(size_t)E_DIM * N_DIM * H_DIM];         // w2 fp16 straight
__device__ uint32_t g_xh [(size_t)A_DIM * M_DIM * (H_DIM / 2)];   // x  fp16 (words)
__device__ float    g_part[(size_t)E_DIM * SPLITK_C * H_DIM * H_DIM]; // fp32 partials
__device__ __half   g_wsh[(size_t)H_DIM * H_DIM];                 // wsum fp16 [k][n]

// ---------------- helpers ----------------
__device__ __forceinline__ uint32_t smem_u32(const void* p) {
    uint32_t a;
    asm("{ .reg .u64 t; cvta.to.shared.u64 t, %1; cvt.u32.u64 %0, t; }" : "=r"(a) : "l"(p));
    return a;
}
__device__ __forceinline__ uint32_t pack_h2(float lo, float hi) {
    __half2 h = __float22half2_rn(make_float2(lo, hi));
    return *reinterpret_cast<uint32_t*>(&h);
}
__device__ __forceinline__ void cp16(uint32_t dst, const void* src) {
    asm volatile("cp.async.cg.shared.global [%0], [%1], 16;\n"
                 :: "r"(dst), "l"(__cvta_generic_to_global(src)) : "memory");
}
__device__ __forceinline__ void mma_f16(float* c, const uint32_t* a, const uint32_t* b) {
    asm volatile(
        "mma.sync.aligned.m16n8k16.row.col.f32.f16.f16.f32 "
        "{%0,%1,%2,%3}, {%4,%5,%6,%7}, {%8,%9}, {%0,%1,%2,%3};"
        : "+f"(c[0]), "+f"(c[1]), "+f"(c[2]), "+f"(c[3])
        : "r"(a[0]), "r"(a[1]), "r"(a[2]), "r"(a[3]), "r"(b[0]), "r"(b[1]));
}
__device__ __forceinline__ void ldsm4(uint32_t addr, uint32_t* r) {
    asm volatile("ldmatrix.sync.aligned.m8n8.x4.shared.b16 {%0,%1,%2,%3}, [%4];"
                 : "=r"(r[0]), "=r"(r[1]), "=r"(r[2]), "=r"(r[3]) : "r"(addr));
}
__device__ __forceinline__ void ldsm4t(uint32_t addr, uint32_t& r0, uint32_t& r1,
                                       uint32_t& r2, uint32_t& r3) {
    asm volatile("ldmatrix.sync.aligned.m8n8.x4.trans.shared.b16 {%0,%1,%2,%3}, [%4];"
                 : "=r"(r0), "=r"(r1), "=r"(r2), "=r"(r3) : "r"(addr));
}

// ---- prep: fp32 -> fp16 streaming conversion ----
__global__ void conv_h_ker(const float* __restrict__ src, uint32_t* __restrict__ dst) {
    size_t i = (size_t)blockIdx.x * blockDim.x + threadIdx.x;
    float4 v = reinterpret_cast<const float4*>(src)[i];
    uint2 o;
    o.x = pack_h2(v.x, v.y);
    o.y = pack_h2(v.z, v.w);
    reinterpret_cast<uint2*>(dst)[i] = o;
}

// =============================================================================
// fp16 GEMM, ldmatrix edition.
// A: fp16 words [m][k/2] straight. B: fp16 halves [k][n] straight.
// C: fp32. 2 CTA/SM, NSTAGE=3, cross-kb fragment pipeline.
// =============================================================================
template <int KB, int SPLITK>
__global__ void __launch_bounds__(NTHREADS, 2)
gemm_f16_ker(const uint32_t* __restrict__ Ag, const __half* __restrict__ Bg,
             float* __restrict__ Cg,
             int lda_w, int ldb_h, int ldc,
             size_t a_batch, size_t b_batch, size_t c_batch) {
    extern __shared__ uint32_t sm[];

    const int tid  = threadIdx.x;
    const int lane = tid & 31;
    const int warp = tid >> 5;
    const int g = lane >> 2;
    const int q = lane & 3;
    const int wm = warp & 1;
    const int wn = warp >> 1;

    const int bz = blockIdx.z;
    const int zo = bz / SPLITK;
    const int sk = bz % SPLITK;

    const uint32_t* A = Ag + (size_t)zo * a_batch + (size_t)sk * KB * (BKH / 2)
                           + (size_t)blockIdx.y * BM * lda_w;
    const __half*   B = Bg + (size_t)zo * b_batch + (size_t)sk * KB * BKH * ldb_h
                           + (size_t)blockIdx.x * BN;
    float*          C = Cg + (size_t)bz * c_batch
                           + (size_t)blockIdx.y * BM * ldc + (size_t)blockIdx.x * BN;

    const uint32_t smem0 = smem_u32(sm);

    // ---- gmem -> smem geometry (16B chunks) ----
    const int ar = tid >> 3;            // A row (0..15), +16*i; 8 chunks/row of 32 words
    const int ac = (tid & 7) * 4;       // A word col
    const int brow = tid >> 4;          // B k-row (0..7), +8*i; 16 chunks/row of 128 halves
    const int bcol = (tid & 15) * 8;    // B half col

    auto load_stage = [&](int slot, int kb) {
        uint32_t sa = smem0 + (uint32_t)slot * STG_BYTES;
        uint32_t sb = sa + A_STG_WORDS * 4;
        const uint32_t* Ak = A + (size_t)kb * (BKH / 2);
        const __half*   Bk = B + (size_t)kb * BKH * ldb_h;
        #pragma unroll
        for (int i = 0; i < 8; i++) {
            int r = ar + 16 * i;
            cp16(sa + (uint32_t)(r * LDA_W + ac) * 4u, Ak + (size_t)r * lda_w + ac);
        }
        #pragma unroll
        for (int i = 0; i < 8; i++) {
            int r = brow + 8 * i;
            cp16(sb + (uint32_t)(r * LDB_H + bcol) * 2u, Bk + (size_t)r * ldb_h + bcol);
        }
        asm volatile("cp.async.commit_group;\n" ::: "memory");
    };

    // ---- per-lane ldmatrix base offsets (bytes) ----
    const int l8  = lane & 7;
    const int lb8 = (lane >> 3) & 1;
    const int lhi = lane >> 4;
    // A: row = wm*64 [+mt*16] + l8 + 8*lb8 ; word col = [ks*8] + 4*lhi
    const uint32_t a_off = (uint32_t)((wm * 64 + l8 + 8 * lb8) * LDA_W + 4 * lhi) * 4u;
    // B: k-row = [ks*16] + l8 + 8*lb8 ; n col = wn*64 [+p*16] + 8*lhi
    const uint32_t b_off = (uint32_t)((l8 + 8 * lb8) * LDB_H + wn * 64 + 8 * lhi) * 2u;

    // ---- accumulators ----
    float c[4][8][4];
    #pragma unroll
    for (int mt = 0; mt < 4; mt++)
        #pragma unroll
        for (int nt = 0; nt < 8; nt++)
            #pragma unroll
            for (int i = 0; i < 4; i++) c[mt][nt][i] = 0.0f;

    uint32_t afr[2][4][4];
    uint32_t bfr[2][8][2];

    auto load_frags = [&](uint32_t sa, uint32_t sb, int ks, int buf) {
        uint32_t abase = sa + a_off + (uint32_t)ks * 32u;           // ks*8 words
        #pragma unroll
        for (int mt = 0; mt < 4; mt++)
            ldsm4(abase + (uint32_t)(mt * 16 * LDA_W) * 4u, afr[buf][mt]);
        uint32_t bbase = sb + b_off + (uint32_t)(ks * 16 * LDB_H) * 2u;
        #pragma unroll
        for (int p = 0; p < 4; p++)
            ldsm4t(bbase + (uint32_t)p * 32u,                       // p*16 halves
                   bfr[buf][2 * p][0], bfr[buf][2 * p][1],
                   bfr[buf][2 * p + 1][0], bfr[buf][2 * p + 1][1]);
    };

    auto mma_batch = [&](int buf) {
        #pragma unroll
        for (int mt = 0; mt < 4; mt++)
            #pragma unroll
            for (int nt = 0; nt < 8; nt++)
                mma_f16(c[mt][nt], afr[buf][mt], bfr[buf][nt]);
    };

    // ---- prologue ----
    load_stage(0, 0);
    load_stage(1, 1);
    asm volatile("cp.async.wait_group 1;\n" ::: "memory");
    __syncthreads();
    load_frags(smem0, smem0 + A_STG_WORDS * 4, 0, 0);

    int slot_c = 0, slot_p = 2;

    // ---- main loop (R7 seam structure) ----
    #pragma unroll 1
    for (int kb = 0; kb < KB; ++kb) {
        uint32_t sa = smem0 + (uint32_t)slot_c * STG_BYTES;
        uint32_t sb = sa + A_STG_WORDS * 4;

        load_frags(sa, sb, 1, 1);
        mma_batch(0);
        load_frags(sa, sb, 2, 0);
        mma_batch(1);
        load_frags(sa, sb, 3, 1);
        mma_batch(0);

        asm volatile("cp.async.wait_group 0;\n" ::: "memory");
        __syncthreads();
        int pf = kb + NSTAGE - 1;
        if (pf < KB) load_stage(slot_p, pf);
        if (++slot_p == NSTAGE) slot_p = 0;

        int slot_n = (slot_c + 1 == NSTAGE) ? 0 : slot_c + 1;
        if (kb + 1 < KB) {
            uint32_t sn = smem0 + (uint32_t)slot_n * STG_BYTES;
            load_frags(sn, sn + A_STG_WORDS * 4, 0, 0);
        }
        mma_batch(1);
        slot_c = slot_n;
    }

    // ---- epilogue (fp32) ----
    #pragma unroll
    for (int mt = 0; mt < 4; mt++) {
        #pragma unroll
        for (int nt = 0; nt < 8; nt++) {
            int r0  = wm * 64 + mt * 16 + g;
            int col = wn * 64 + nt * 8 + 2 * q;
            float2 v0 = make_float2(c[mt][nt][0], c[mt][nt][1]);
            float2 v1 = make_float2(c[mt][nt][2], c[mt][nt][3]);
            *reinterpret_cast<float2*>(C + (size_t)r0 * ldc + col)       = v0;
            *reinterpret_cast<float2*>(C + (size_t)(r0 + 8) * ldc + col) = v1;
        }
    }
}

// ---- reduce 32 fp32 partials -> fp16 wsum halves [k][n] ----
__global__ void reduce_experts_ker() {
    int idx = blockIdx.x * blockDim.x + threadIdx.x;   // 1024 k x 128 n8
    int n8 = idx & 127;
    int k  = idx >> 7;
    const float4* p = reinterpret_cast<const float4*>(g_part);
    size_t base = (size_t)k * (H_DIM / 4) + n8 * 2;
    float4 a0 = make_float4(0.f, 0.f, 0.f, 0.f), a1 = a0;
    #pragma unroll
    for (int e = 0; e < E_DIM * SPLITK_C; e++) {
        size_t pl = (size_t)e * (H_DIM * H_DIM / 4) + base;
        float4 v0 = p[pl];
        float4 v1 = p[pl + 1];
        a0.x += v0.x; a0.y += v0.y; a0.z += v0.z; a0.w += v0.w;
        a1.x += v1.x; a1.y += v1.y; a1.z += v1.z; a1.w += v1.w;
    }
    uint4 o;
    o.x = pack_h2(a0.x, a0.y);
    o.y = pack_h2(a0.z, a0.w);
    o.z = pack_h2(a1.x, a1.y);
    o.w = pack_h2(a1.z, a1.w);
    reinterpret_cast<uint4*>(g_wsh)[idx] = o;
}

// ================= launch =================
extern "C" void kernel_launch(void* const* d_in, const int* in_sizes, int n_in,
                              void* d_out, int out_size) {
    const float* x  = (const float*)d_in[0];
    const float* w1 = (const float*)d_in[1];   // [E][H][N]
    const float* w2 = (const float*)d_in[2];   // [E][N][H]
    float* out = (float*)d_out;                // [A][M][H]

    uint32_t* w1h = nullptr; cudaGetSymbolAddress((void**)&w1h, g_w1h);
    __half*   w2h = nullptr; cudaGetSymbolAddress((void**)&w2h, g_w2h);
    uint32_t* xh  = nullptr; cudaGetSymbolAddress((void**)&xh,  g_xh);
    float*    part = nullptr; cudaGetSymbolAddress((void**)&part, g_part);
    __half*   wsh = nullptr; cudaGetSymbolAddress((void**)&wsh, g_wsh);

    constexpr int KB_C = (N_DIM / BKH) / SPLITK_C;  // 16 kb per combine CTA
    constexpr int KB_A = H_DIM / BKH;               // 16 kb for apply

    cudaFuncSetAttribute((const void*)gemm_f16_ker<KB_C, SPLITK_C>,
                         cudaFuncAttributeMaxDynamicSharedMemorySize, SMEM_DYN);
    cudaFuncSetAttribute((const void*)gemm_f16_ker<KB_A, 1>,
                         cudaFuncAttributeMaxDynamicSharedMemorySize, SMEM_DYN);

    // 0) fp16 conversions (all straight element-wise)
    conv_h_ker<<<(int)(((size_t)E_DIM * H_DIM * N_DIM / 4) / 256), 256>>>(w1, w1h);
    conv_h_ker<<<(int)(((size_t)E_DIM * N_DIM * H_DIM / 4) / 256), 256>>>(
        w2, (uint32_t*)w2h);
    conv_h_ker<<<(A_DIM * M_DIM * H_DIM / 4) / 256, 256>>>(x, xh);

    // 1) per-expert split-K combine: g_part[e*4+s] = w1h[e]_Ks @ w2h[e]_Ks
    gemm_f16_ker<KB_C, SPLITK_C>
        <<<dim3(H_DIM / BN, H_DIM / BM, E_DIM * SPLITK_C), NTHREADS, SMEM_DYN>>>(
            w1h, w2h, part,
            N_DIM / 2, H_DIM, H_DIM,
            (size_t)H_DIM * (N_DIM / 2), (size_t)N_DIM * H_DIM,
            (size_t)H_DIM * H_DIM);

    // 2) reduce partials -> fp16 wsum [k][n]
    reduce_experts_ker<<<H_DIM * (H_DIM / 8) / 256, 256>>>();

    // 3) apply: out = xh @ wsum
    gemm_f16_ker<KB_A, 1>
        <<<dim3(H_DIM / BN, (A_DIM * M_DIM) / BM, 1), NTHREADS, SMEM_DYN>>>(
            xh, wsh, out,
            H_DIM / 2, H_DIM, H_DIM,
            0, 0, 0);
}

// round 12
// speedup vs baseline: 2.4775x; 1.0361x over previous
#include <cuda_runtime.h>
#include <cuda_fp16.h>
#include <cstdint>
#include <cstddef>

// ---------------- problem dims ----------------
#define A_DIM 4
#define M_DIM 1024
#define H_DIM 1024
#define E_DIM 8
#define N_DIM 4096
#define SPLITK_C 4

// ---------------- tile config ----------------
#define BM 128
#define BN 128
#define BKH 64          /* K-halves per kb-iter */
#define NSTAGE 3
#define NTHREADS 128    /* 4 warps, warp tile 64x64 */
#define LDA_W 36        /* A stage row stride in words */
#define LDB_H 136       /* B stage row stride in halves */
#define A_STG_WORDS (BM * LDA_W)            /* 4608 words */
#define B_STG_WORDS (BKH * LDB_H / 2)       /* 4352 words */
#define STG_WORDS   (A_STG_WORDS + B_STG_WORDS)
#define STG_BYTES   (STG_WORDS * 4)                /* 35840 B */
#define SMEM_DYN    (NSTAGE * STG_BYTES)           /* 107520 B -> 2 CTA/SM */
#define GRID_P      296                            /* 2 x 148 SMs */

// ---------------- device scratch ----------------
__device__ uint32_t g_w1h[(size_t)E_DIM * H_DIM * (N_DIM / 2)];
__device__ __half   g_w2h[(size_t)E_DIM * N_DIM * H_DIM];
__device__ uint32_t g_xh [(size_t)A_DIM * M_DIM * (H_DIM / 2)];
__device__ float    g_part[(size_t)E_DIM * SPLITK_C * H_DIM * H_DIM];
__device__ __half   g_wsh[(size_t)H_DIM * H_DIM];

// ---------------- helpers ----------------
__device__ __forceinline__ uint32_t smem_u32(const void* p) {
    uint32_t a;
    asm("{ .reg .u64 t; cvta.to.shared.u64 t, %1; cvt.u32.u64 %0, t; }" : "=r"(a) : "l"(p));
    return a;
}
__device__ __forceinline__ uint32_t pack_h2(float lo, float hi) {
    __half2 h = __float22half2_rn(make_float2(lo, hi));
    return *reinterpret_cast<uint32_t*>(&h);
}
__device__ __forceinline__ void cp16(uint32_t dst, const void* src) {
    asm volatile("cp.async.cg.shared.global [%0], [%1], 16;\n"
                 :: "r"(dst), "l"(__cvta_generic_to_global(src)) : "memory");
}
__device__ __forceinline__ void mma_f16(float* c, const uint32_t* a, const uint32_t* b) {
    asm volatile(
        "mma.sync.aligned.m16n8k16.row.col.f32.f16.f16.f32 "
        "{%0,%1,%2,%3}, {%4,%5,%6,%7}, {%8,%9}, {%0,%1,%2,%3};"
        : "+f"(c[0]), "+f"(c[1]), "+f"(c[2]), "+f"(c[3])
        : "r"(a[0]), "r"(a[1]), "r"(a[2]), "r"(a[3]), "r"(b[0]), "r"(b[1]));
}
__device__ __forceinline__ void ldsm4(uint32_t addr, uint32_t* r) {
    asm volatile("ldmatrix.sync.aligned.m8n8.x4.shared.b16 {%0,%1,%2,%3}, [%4];"
                 : "=r"(r[0]), "=r"(r[1]), "=r"(r[2]), "=r"(r[3]) : "r"(addr));
}
__device__ __forceinline__ void ldsm4t(uint32_t addr, uint32_t& r0, uint32_t& r1,
                                       uint32_t& r2, uint32_t& r3) {
    asm volatile("ldmatrix.sync.aligned.m8n8.x4.trans.shared.b16 {%0,%1,%2,%3}, [%4];"
                 : "=r"(r0), "=r"(r1), "=r"(r2), "=r"(r3) : "r"(addr));
}

// ---- prep: fp32 -> fp16 streaming conversion ----
__global__ void conv_h_ker(const float* __restrict__ src, uint32_t* __restrict__ dst) {
    size_t i = (size_t)blockIdx.x * blockDim.x + threadIdx.x;
    float4 v = reinterpret_cast<const float4*>(src)[i];
    uint2 o;
    o.x = pack_h2(v.x, v.y);
    o.y = pack_h2(v.z, v.w);
    reinterpret_cast<uint2*>(dst)[i] = o;
}

// =============================================================================
// Persistent fp16 GEMM. A: fp16 words [m][k/2]. B: fp16 halves [k][n]. C: fp32.
// Tiles decoded t -> (bx = t&7, by, bz); each CTA walks t += gridDim.x with a
// continuous cp.async stage ring across tile boundaries.
// =============================================================================
template <int KB, int SPLITK, int NYL2, int NT,
          int LDAW, int LDBH, int LDC,
          size_t ABATCH, size_t BBATCH, size_t CBATCH>
__global__ void __launch_bounds__(NTHREADS, 2)
gemm_f16_ker(const uint32_t* __restrict__ Ag, const __half* __restrict__ Bg,
             float* __restrict__ Cg) {
    extern __shared__ uint32_t sm[];

    const int tid  = threadIdx.x;
    const int lane = tid & 31;
    const int warp = tid >> 5;
    const int g = lane >> 2;
    const int q = lane & 3;
    const int wm = warp & 1;
    const int wn = warp >> 1;

    const uint32_t smem0 = smem_u32(sm);

    // gmem->smem geometry (16B chunks)
    const int ar = tid >> 3;
    const int ac = (tid & 7) * 4;
    const int brow = tid >> 4;
    const int bcol = (tid & 15) * 8;

    auto tile_ab = [&](int t, const uint32_t*& A, const __half*& B) {
        int bx = t & 7;
        int by = (t >> 3) & ((1 << NYL2) - 1);
        int bz = t >> (3 + NYL2);
        int zo = bz / SPLITK, sk = bz % SPLITK;
        A = Ag + (size_t)zo * ABATCH + (size_t)sk * (KB * BKH / 2)
               + (size_t)by * BM * LDAW;
        B = Bg + (size_t)zo * BBATCH + (size_t)sk * (KB * BKH) * LDBH
               + (size_t)bx * BN;
    };

    auto load_stage = [&](int slot, const uint32_t* A, const __half* B, int kb) {
        uint32_t sa = smem0 + (uint32_t)slot * STG_BYTES;
        uint32_t sb = sa + A_STG_WORDS * 4;
        const uint32_t* Ak = A + (size_t)kb * (BKH / 2);
        const __half*   Bk = B + (size_t)kb * BKH * LDBH;
        #pragma unroll
        for (int i = 0; i < 8; i++) {
            int r = ar + 16 * i;
            cp16(sa + (uint32_t)(r * LDA_W + ac) * 4u, Ak + (size_t)r * LDAW + ac);
        }
        #pragma unroll
        for (int i = 0; i < 8; i++) {
            int r = brow + 8 * i;
            cp16(sb + (uint32_t)(r * LDB_H + bcol) * 2u, Bk + (size_t)r * LDBH + bcol);
        }
        asm volatile("cp.async.commit_group;\n" ::: "memory");
    };

    // per-lane ldmatrix offsets
    const int l8  = lane & 7;
    const int lb8 = (lane >> 3) & 1;
    const int lhi = lane >> 4;
    const uint32_t a_off = (uint32_t)((wm * 64 + l8 + 8 * lb8) * LDA_W + 4 * lhi) * 4u;
    const uint32_t b_off = (uint32_t)((l8 + 8 * lb8) * LDB_H + wn * 64 + 8 * lhi) * 2u;

    float c[4][8][4];
    #pragma unroll
    for (int mt = 0; mt < 4; mt++)
        #pragma unroll
        for (int nt = 0; nt < 8; nt++)
            #pragma unroll
            for (int i = 0; i < 4; i++) c[mt][nt][i] = 0.0f;

    uint32_t afr[2][4][4];
    uint32_t bfr[2][8][2];

    auto load_frags = [&](int slot, int ks, int buf) {
        uint32_t sa = smem0 + (uint32_t)slot * STG_BYTES;
        uint32_t sb = sa + A_STG_WORDS * 4;
        uint32_t abase = sa + a_off + (uint32_t)ks * 32u;
        #pragma unroll
        for (int mt = 0; mt < 4; mt++)
            ldsm4(abase + (uint32_t)(mt * 16 * LDA_W) * 4u, afr[buf][mt]);
        uint32_t bbase = sb + b_off + (uint32_t)(ks * 16 * LDB_H) * 2u;
        #pragma unroll
        for (int p = 0; p < 4; p++)
            ldsm4t(bbase + (uint32_t)p * 32u,
                   bfr[buf][2 * p][0], bfr[buf][2 * p][1],
                   bfr[buf][2 * p + 1][0], bfr[buf][2 * p + 1][1]);
    };

    auto mma_batch = [&](int buf) {
        #pragma unroll
        for (int mt = 0; mt < 4; mt++)
            #pragma unroll
            for (int nt = 0; nt < 8; nt++)
                mma_f16(c[mt][nt], afr[buf][mt], bfr[buf][nt]);
    };

    // ---- current + next tile pointers ----
    int t = blockIdx.x;
    const uint32_t* A0; const __half* B0;
    tile_ab(t, A0, B0);
    int t2 = t + (int)gridDim.x;
    const uint32_t* A1 = A0; const __half* B1 = B0;
    if (t2 < NT) tile_ab(t2, A1, B1);

    // ---- prologue: stages j=0,1 ----
    load_stage(0, A0, B0, 0);
    load_stage(1, A0, B0, 1);
    asm volatile("cp.async.wait_group 1;\n" ::: "memory");
    __syncthreads();
    load_frags(0, 0, 0);

    int slot_c = 0, slot_p = 2;

    // ---- persistent tile loop ----
    while (true) {
        #pragma unroll 1
        for (int kb = 0; kb < KB; ++kb) {
            load_frags(slot_c, 1, 1);
            mma_batch(0);
            load_frags(slot_c, 2, 0);
            mma_batch(1);
            load_frags(slot_c, 3, 1);
            mma_batch(0);

            // seam: issue stage j+2 FIRST, then wait for stage j+1 only
            int pf = kb + 2;
            bool pfc = pf < KB;
            bool pfn = !pfc && (t2 < NT);
            if (pfc)      load_stage(slot_p, A0, B0, pf);
            else if (pfn) load_stage(slot_p, A1, B1, pf - KB);
            if (pfc || pfn)
                asm volatile("cp.async.wait_group 1;\n" ::: "memory");
            else
                asm volatile("cp.async.wait_group 0;\n" ::: "memory");
            __syncthreads();
            if (++slot_p == NSTAGE) slot_p = 0;

            int slot_n = (slot_c + 1 == NSTAGE) ? 0 : slot_c + 1;
            if ((kb + 1 < KB) || (t2 < NT)) load_frags(slot_n, 0, 0);
            mma_batch(1);
            slot_c = slot_n;
        }

        // ---- epilogue for tile t (overlaps next tile's in-flight stages) ----
        {
            int bx = t & 7;
            int by = (t >> 3) & ((1 << NYL2) - 1);
            int bz = t >> (3 + NYL2);
            float* C = Cg + (size_t)bz * CBATCH + (size_t)by * BM * LDC
                          + (size_t)bx * BN;
            #pragma unroll
            for (int mt = 0; mt < 4; mt++) {
                #pragma unroll
                for (int nt = 0; nt < 8; nt++) {
                    int r0  = wm * 64 + mt * 16 + g;
                    int col = wn * 64 + nt * 8 + 2 * q;
                    float2 v0 = make_float2(c[mt][nt][0], c[mt][nt][1]);
                    float2 v1 = make_float2(c[mt][nt][2], c[mt][nt][3]);
                    *reinterpret_cast<float2*>(C + (size_t)r0 * LDC + col)       = v0;
                    *reinterpret_cast<float2*>(C + (size_t)(r0 + 8) * LDC + col) = v1;
                }
            }
        }
        if (t2 >= NT) break;

        // reset accumulators, advance tiles
        #pragma unroll
        for (int mt = 0; mt < 4; mt++)
            #pragma unroll
            for (int nt = 0; nt < 8; nt++)
                #pragma unroll
                for (int i = 0; i < 4; i++) c[mt][nt][i] = 0.0f;
        t = t2; A0 = A1; B0 = B1;
        t2 += (int)gridDim.x;
        if (t2 < NT) tile_ab(t2, A1, B1);
    }
}

// ---- reduce 32 fp32 partials -> fp16 wsum halves [k][n] ----
__global__ void reduce_experts_ker() {
    int idx = blockIdx.x * blockDim.x + threadIdx.x;
    int n8 = idx & 127;
    int k  = idx >> 7;
    const float4* p = reinterpret_cast<const float4*>(g_part);
    size_t base = (size_t)k * (H_DIM / 4) + n8 * 2;
    float4 a0 = make_float4(0.f, 0.f, 0.f, 0.f), a1 = a0;
    #pragma unroll
    for (int e = 0; e < E_DIM * SPLITK_C; e++) {
        size_t pl = (size_t)e * (H_DIM * H_DIM / 4) + base;
        float4 v0 = p[pl];
        float4 v1 = p[pl + 1];
        a0.x += v0.x; a0.y += v0.y; a0.z += v0.z; a0.w += v0.w;
        a1.x += v1.x; a1.y += v1.y; a1.z += v1.z; a1.w += v1.w;
    }
    uint4 o;
    o.x = pack_h2(a0.x, a0.y);
    o.y = pack_h2(a0.z, a0.w);
    o.z = pack_h2(a1.x, a1.y);
    o.w = pack_h2(a1.z, a1.w);
    reinterpret_cast<uint4*>(g_wsh)[idx] = o;
}

// ================= launch =================
extern "C" void kernel_launch(void* const* d_in, const int* in_sizes, int n_in,
                              void* d_out, int out_size) {
    const float* x  = (const float*)d_in[0];
    const float* w1 = (const float*)d_in[1];   // [E][H][N]
    const float* w2 = (const float*)d_in[2];   // [E][N][H]
    float* out = (float*)d_out;                // [A][M][H]

    uint32_t* w1h = nullptr; cudaGetSymbolAddress((void**)&w1h, g_w1h);
    __half*   w2h = nullptr; cudaGetSymbolAddress((void**)&w2h, g_w2h);
    uint32_t* xh  = nullptr; cudaGetSymbolAddress((void**)&xh,  g_xh);
    float*    part = nullptr; cudaGetSymbolAddress((void**)&part, g_part);
    __half*   wsh = nullptr; cudaGetSymbolAddress((void**)&wsh, g_wsh);

    // Combine: tiles = 8 x 8 x (E*SPLITK=32) = 2048 ; KB = (N/BKH)/SPLITK = 16
    using CombineKer = void(const uint32_t*, const __half*, float*);
    constexpr int KB_C = (N_DIM / BKH) / SPLITK_C;
    auto* comb = gemm_f16_ker<KB_C, SPLITK_C, 3, 2048,
                              N_DIM / 2, H_DIM, H_DIM,
                              (size_t)H_DIM * (N_DIM / 2),
                              (size_t)N_DIM * H_DIM,
                              (size_t)H_DIM * H_DIM>;
    // Apply: tiles = 8 x 32 x 1 = 256 ; KB = H/BKH = 16
    constexpr int KB_A = H_DIM / BKH;
    auto* appl = gemm_f16_ker<KB_A, 1, 5, 256,
                              H_DIM / 2, H_DIM, H_DIM,
                              (size_t)0, (size_t)0, (size_t)0>;

    cudaFuncSetAttribute((const void*)comb,
                         cudaFuncAttributeMaxDynamicSharedMemorySize, SMEM_DYN);
    cudaFuncSetAttribute((const void*)appl,
                         cudaFuncAttributeMaxDynamicSharedMemorySize, SMEM_DYN);

    // 0) fp16 conversions
    conv_h_ker<<<(int)(((size_t)E_DIM * H_DIM * N_DIM / 4) / 256), 256>>>(w1, w1h);
    conv_h_ker<<<(int)(((size_t)E_DIM * N_DIM * H_DIM / 4) / 256), 256>>>(
        w2, (uint32_t*)w2h);
    conv_h_ker<<<(A_DIM * M_DIM * H_DIM / 4) / 256, 256>>>(x, xh);

    // 1) persistent split-K combine
    comb<<<GRID_P, NTHREADS, SMEM_DYN>>>(w1h, w2h, part);

    // 2) reduce partials -> fp16 wsum [k][n]
    reduce_experts_ker<<<H_DIM * (H_DIM / 8) / 256, 256>>>();

    // 3) apply: out = xh @ wsum
    appl<<<256, NTHREADS, SMEM_DYN>>>(xh, wsh, out);
}

// round 13
// speedup vs baseline: 2.6358x; 1.0639x over previous
#include <cuda_runtime.h>
#include <cuda_fp16.h>
#include <cstdint>
#include <cstddef>

// ---------------- problem dims ----------------
#define A_DIM 4
#define M_DIM 1024
#define H_DIM 1024
#define E_DIM 8
#define N_DIM 4096
#define SPLITK_C 4

// ---------------- tile config ----------------
#define BM 128
#define BN 128
#define BKH 64          /* K-halves per kb-iter */
#define NSTAGE 3
#define NTHREADS 128    /* 4 warps, warp tile 64x64 */
#define LDA_W 36        /* A stage row stride in words */
#define LDB_H 136       /* B stage row stride in halves */
#define A_STG_WORDS (BM * LDA_W)
#define B_STG_WORDS (BKH * LDB_H / 2)
#define STG_WORDS   (A_STG_WORDS + B_STG_WORDS)
#define STG_BYTES   (STG_WORDS * 4)                /* 35840 B */
#define SMEM_DYN    (NSTAGE * STG_BYTES)           /* 107520 B -> 2 CTA/SM */
#define GRID_P      296

// ---------------- device scratch ----------------
__device__ uint32_t g_w1h[(size_t)E_DIM * H_DIM * (N_DIM / 2)];
__device__ __half   g_w2h[(size_t)E_DIM * N_DIM * H_DIM];
__device__ uint32_t g_xh [(size_t)A_DIM * M_DIM * (H_DIM / 2)];
__device__ __half   g_part[(size_t)E_DIM * SPLITK_C * H_DIM * H_DIM];  // 64 MB fp16
__device__ __half   g_wsh[(size_t)H_DIM * H_DIM];

// ---------------- helpers ----------------
__device__ __forceinline__ uint32_t smem_u32(const void* p) {
    uint32_t a;
    asm("{ .reg .u64 t; cvta.to.shared.u64 t, %1; cvt.u32.u64 %0, t; }" : "=r"(a) : "l"(p));
    return a;
}
__device__ __forceinline__ uint32_t pack_h2(float lo, float hi) {
    __half2 h = __float22half2_rn(make_float2(lo, hi));
    return *reinterpret_cast<uint32_t*>(&h);
}
__device__ __forceinline__ void cp16(uint32_t dst, const void* src) {
    asm volatile("cp.async.cg.shared.global [%0], [%1], 16;\n"
                 :: "r"(dst), "l"(__cvta_generic_to_global(src)) : "memory");
}
__device__ __forceinline__ void mma_f16(float* c, const uint32_t* a, const uint32_t* b) {
    asm volatile(
        "mma.sync.aligned.m16n8k16.row.col.f32.f16.f16.f32 "
        "{%0,%1,%2,%3}, {%4,%5,%6,%7}, {%8,%9}, {%0,%1,%2,%3};"
        : "+f"(c[0]), "+f"(c[1]), "+f"(c[2]), "+f"(c[3])
        : "r"(a[0]), "r"(a[1]), "r"(a[2]), "r"(a[3]), "r"(b[0]), "r"(b[1]));
}
__device__ __forceinline__ void ldsm4(uint32_t addr, uint32_t* r) {
    asm volatile("ldmatrix.sync.aligned.m8n8.x4.shared.b16 {%0,%1,%2,%3}, [%4];"
                 : "=r"(r[0]), "=r"(r[1]), "=r"(r[2]), "=r"(r[3]) : "r"(addr));
}
__device__ __forceinline__ void ldsm4t(uint32_t addr, uint32_t& r0, uint32_t& r1,
                                       uint32_t& r2, uint32_t& r3) {
    asm volatile("ldmatrix.sync.aligned.m8n8.x4.trans.shared.b16 {%0,%1,%2,%3}, [%4];"
                 : "=r"(r0), "=r"(r1), "=r"(r2), "=r"(r3) : "r"(addr));
}

// ---- prep: single fused fp32 -> fp16 conversion over w1, w2, x ----
#define N4_W1 ((size_t)E_DIM * H_DIM * N_DIM / 4)
#define N4_W2 ((size_t)E_DIM * N_DIM * H_DIM / 4)
#define N4_X  ((size_t)A_DIM * M_DIM * H_DIM / 4)
__global__ void conv_all_ker(const float* __restrict__ x,
                             const float* __restrict__ w1,
                             const float* __restrict__ w2) {
    size_t i = (size_t)blockIdx.x * blockDim.x + threadIdx.x;
    const float* src; uint32_t* dst; size_t j;
    if (i < N4_W1)              { src = w1; dst = g_w1h;            j = i; }
    else if (i < N4_W1 + N4_W2) { src = w2; dst = (uint32_t*)g_w2h; j = i - N4_W1; }
    else                        { src = x;  dst = g_xh;             j = i - N4_W1 - N4_W2; }
    float4 v = reinterpret_cast<const float4*>(src)[j];
    uint2 o;
    o.x = pack_h2(v.x, v.y);
    o.y = pack_h2(v.z, v.w);
    reinterpret_cast<uint2*>(dst)[j] = o;
}

// =============================================================================
// Persistent fp16 GEMM. A: fp16 words [m][k/2]. B: fp16 halves [k][n].
// OUT_HALF: write C as fp16 (combine partials) or fp32 (final output).
// =============================================================================
template <int KB, int SPLITK, int NYL2, int NT, bool OUT_HALF,
          int LDAW, int LDBH, int LDC,
          size_t ABATCH, size_t BBATCH, size_t CBATCH>
__global__ void __launch_bounds__(NTHREADS, 2)
gemm_f16_ker(const uint32_t* __restrict__ Ag, const __half* __restrict__ Bg,
             void* __restrict__ Cg) {
    extern __shared__ uint32_t sm[];

    const int tid  = threadIdx.x;
    const int lane = tid & 31;
    const int warp = tid >> 5;
    const int g = lane >> 2;
    const int q = lane & 3;
    const int wm = warp & 1;
    const int wn = warp >> 1;

    const uint32_t smem0 = smem_u32(sm);

    const int ar = tid >> 3;
    const int ac = (tid & 7) * 4;
    const int brow = tid >> 4;
    const int bcol = (tid & 15) * 8;

    auto tile_ab = [&](int t, const uint32_t*& A, const __half*& B) {
        int bx = t & 7;
        int by = (t >> 3) & ((1 << NYL2) - 1);
        int bz = t >> (3 + NYL2);
        int zo = bz / SPLITK, sk = bz % SPLITK;
        A = Ag + (size_t)zo * ABATCH + (size_t)sk * (KB * BKH / 2)
               + (size_t)by * BM * LDAW;
        B = Bg + (size_t)zo * BBATCH + (size_t)sk * (KB * BKH) * LDBH
               + (size_t)bx * BN;
    };

    auto load_stage = [&](int slot, const uint32_t* A, const __half* B, int kb) {
        uint32_t sa = smem0 + (uint32_t)slot * STG_BYTES;
        uint32_t sb = sa + A_STG_WORDS * 4;
        const uint32_t* Ak = A + (size_t)kb * (BKH / 2);
        const __half*   Bk = B + (size_t)kb * BKH * LDBH;
        #pragma unroll
        for (int i = 0; i < 8; i++) {
            int r = ar + 16 * i;
            cp16(sa + (uint32_t)(r * LDA_W + ac) * 4u, Ak + (size_t)r * LDAW + ac);
        }
        #pragma unroll
        for (int i = 0; i < 8; i++) {
            int r = brow + 8 * i;
            cp16(sb + (uint32_t)(r * LDB_H + bcol) * 2u, Bk + (size_t)r * LDBH + bcol);
        }
        asm volatile("cp.async.commit_group;\n" ::: "memory");
    };

    const int l8  = lane & 7;
    const int lb8 = (lane >> 3) & 1;
    const int lhi = lane >> 4;
    const uint32_t a_off = (uint32_t)((wm * 64 + l8 + 8 * lb8) * LDA_W + 4 * lhi) * 4u;
    const uint32_t b_off = (uint32_t)((l8 + 8 * lb8) * LDB_H + wn * 64 + 8 * lhi) * 2u;

    float c[4][8][4];
    #pragma unroll
    for (int mt = 0; mt < 4; mt++)
        #pragma unroll
        for (int nt = 0; nt < 8; nt++)
            #pragma unroll
            for (int i = 0; i < 4; i++) c[mt][nt][i] = 0.0f;

    uint32_t afr[2][4][4];
    uint32_t bfr[2][8][2];

    auto load_frags = [&](int slot, int ks, int buf) {
        uint32_t sa = smem0 + (uint32_t)slot * STG_BYTES;
        uint32_t sb = sa + A_STG_WORDS * 4;
        uint32_t abase = sa + a_off + (uint32_t)ks * 32u;
        #pragma unroll
        for (int mt = 0; mt < 4; mt++)
            ldsm4(abase + (uint32_t)(mt * 16 * LDA_W) * 4u, afr[buf][mt]);
        uint32_t bbase = sb + b_off + (uint32_t)(ks * 16 * LDB_H) * 2u;
        #pragma unroll
        for (int p = 0; p < 4; p++)
            ldsm4t(bbase + (uint32_t)p * 32u,
                   bfr[buf][2 * p][0], bfr[buf][2 * p][1],
                   bfr[buf][2 * p + 1][0], bfr[buf][2 * p + 1][1]);
    };

    auto mma_batch = [&](int buf) {
        #pragma unroll
        for (int mt = 0; mt < 4; mt++)
            #pragma unroll
            for (int nt = 0; nt < 8; nt++)
                mma_f16(c[mt][nt], afr[buf][mt], bfr[buf][nt]);
    };

    int t = blockIdx.x;
    const uint32_t* A0; const __half* B0;
    tile_ab(t, A0, B0);
    int t2 = t + (int)gridDim.x;
    const uint32_t* A1 = A0; const __half* B1 = B0;
    if (t2 < NT) tile_ab(t2, A1, B1);

    load_stage(0, A0, B0, 0);
    load_stage(1, A0, B0, 1);
    asm volatile("cp.async.wait_group 1;\n" ::: "memory");
    __syncthreads();
    load_frags(0, 0, 0);

    int slot_c = 0, slot_p = 2;

    while (true) {
        #pragma unroll 1
        for (int kb = 0; kb < KB; ++kb) {
            load_frags(slot_c, 1, 1);
            mma_batch(0);
            load_frags(slot_c, 2, 0);
            mma_batch(1);
            load_frags(slot_c, 3, 1);
            mma_batch(0);

            int pf = kb + 2;
            bool pfc = pf < KB;
            bool pfn = !pfc && (t2 < NT);
            if (pfc)      load_stage(slot_p, A0, B0, pf);
            else if (pfn) load_stage(slot_p, A1, B1, pf - KB);
            if (pfc || pfn)
                asm volatile("cp.async.wait_group 1;\n" ::: "memory");
            else
                asm volatile("cp.async.wait_group 0;\n" ::: "memory");
            __syncthreads();
            if (++slot_p == NSTAGE) slot_p = 0;

            int slot_n = (slot_c + 1 == NSTAGE) ? 0 : slot_c + 1;
            if ((kb + 1 < KB) || (t2 < NT)) load_frags(slot_n, 0, 0);
            mma_batch(1);
            slot_c = slot_n;
        }

        // ---- epilogue for tile t ----
        {
            int bx = t & 7;
            int by = (t >> 3) & ((1 << NYL2) - 1);
            int bz = t >> (3 + NYL2);
            if constexpr (OUT_HALF) {
                __half* C = (__half*)Cg + (size_t)bz * CBATCH
                          + (size_t)by * BM * LDC + (size_t)bx * BN;
                #pragma unroll
                for (int mt = 0; mt < 4; mt++) {
                    #pragma unroll
                    for (int nt = 0; nt < 8; nt++) {
                        int r0  = wm * 64 + mt * 16 + g;
                        int col = wn * 64 + nt * 8 + 2 * q;
                        uint32_t h0 = pack_h2(c[mt][nt][0], c[mt][nt][1]);
                        uint32_t h1 = pack_h2(c[mt][nt][2], c[mt][nt][3]);
                        *reinterpret_cast<uint32_t*>(C + (size_t)r0 * LDC + col)       = h0;
                        *reinterpret_cast<uint32_t*>(C + (size_t)(r0 + 8) * LDC + col) = h1;
                    }
                }
            } else {
                float* C = (float*)Cg + (size_t)bz * CBATCH
                         + (size_t)by * BM * LDC + (size_t)bx * BN;
                #pragma unroll
                for (int mt = 0; mt < 4; mt++) {
                    #pragma unroll
                    for (int nt = 0; nt < 8; nt++) {
                        int r0  = wm * 64 + mt * 16 + g;
                        int col = wn * 64 + nt * 8 + 2 * q;
                        float2 v0 = make_float2(c[mt][nt][0], c[mt][nt][1]);
                        float2 v1 = make_float2(c[mt][nt][2], c[mt][nt][3]);
                        *reinterpret_cast<float2*>(C + (size_t)r0 * LDC + col)       = v0;
                        *reinterpret_cast<float2*>(C + (size_t)(r0 + 8) * LDC + col) = v1;
                    }
                }
            }
        }
        if (t2 >= NT) break;

        #pragma unroll
        for (int mt = 0; mt < 4; mt++)
            #pragma unroll
            for (int nt = 0; nt < 8; nt++)
                #pragma unroll
                for (int i = 0; i < 4; i++) c[mt][nt][i] = 0.0f;
        t = t2; A0 = A1; B0 = B1;
        t2 += (int)gridDim.x;
        if (t2 < NT) tile_ab(t2, A1, B1);
    }
}

// ---- reduce 32 fp16 partials -> fp16 wsum halves [k][n] ----
__global__ void reduce_experts_ker() {
    int idx = blockIdx.x * blockDim.x + threadIdx.x;   // over H*H/8
    const uint4* p = reinterpret_cast<const uint4*>(g_part);
    float acc[8];
    #pragma unroll
    for (int j = 0; j < 8; j++) acc[j] = 0.0f;
    #pragma unroll
    for (int e = 0; e < E_DIM * SPLITK_C; e++) {
        uint4 v = p[(size_t)e * (H_DIM * H_DIM / 8) + idx];
        const __half2* h = reinterpret_cast<const __half2*>(&v);
        #pragma unroll
        for (int j = 0; j < 4; j++) {
            float2 f = __half22float2(h[j]);
            acc[2 * j]     += f.x;
            acc[2 * j + 1] += f.y;
        }
    }
    uint4 o;
    o.x = pack_h2(acc[0], acc[1]);
    o.y = pack_h2(acc[2], acc[3]);
    o.z = pack_h2(acc[4], acc[5]);
    o.w = pack_h2(acc[6], acc[7]);
    reinterpret_cast<uint4*>(g_wsh)[idx] = o;
}

// ================= launch =================
extern "C" void kernel_launch(void* const* d_in, const int* in_sizes, int n_in,
                              void* d_out, int out_size) {
    const float* x  = (const float*)d_in[0];
    const float* w1 = (const float*)d_in[1];   // [E][H][N]
    const float* w2 = (const float*)d_in[2];   // [E][N][H]
    float* out = (float*)d_out;                // [A][M][H]

    uint32_t* w1h = nullptr; cudaGetSymbolAddress((void**)&w1h, g_w1h);
    __half*   w2h = nullptr; cudaGetSymbolAddress((void**)&w2h, g_w2h);
    uint32_t* xh  = nullptr; cudaGetSymbolAddress((void**)&xh,  g_xh);
    __half*   part = nullptr; cudaGetSymbolAddress((void**)&part, g_part);
    __half*   wsh = nullptr; cudaGetSymbolAddress((void**)&wsh, g_wsh);

    constexpr int KB_C = (N_DIM / BKH) / SPLITK_C;
    auto* comb = gemm_f16_ker<KB_C, SPLITK_C, 3, 2048, true,
                              N_DIM / 2, H_DIM, H_DIM,
                              (size_t)H_DIM * (N_DIM / 2),
                              (size_t)N_DIM * H_DIM,
                              (size_t)H_DIM * H_DIM>;
    constexpr int KB_A = H_DIM / BKH;
    auto* appl = gemm_f16_ker<KB_A, 1, 5, 256, false,
                              H_DIM / 2, H_DIM, H_DIM,
                              (size_t)0, (size_t)0, (size_t)0>;

    cudaFuncSetAttribute((const void*)comb,
                         cudaFuncAttributeMaxDynamicSharedMemorySize, SMEM_DYN);
    cudaFuncSetAttribute((const void*)appl,
                         cudaFuncAttributeMaxDynamicSharedMemorySize, SMEM_DYN);

    // 0) fused fp16 conversion of w1, w2, x
    size_t n4_total = N4_W1 + N4_W2 + N4_X;
    conv_all_ker<<<(int)((n4_total + 255) / 256), 256>>>(x, w1, w2);

    // 1) persistent split-K combine -> fp16 partials
    comb<<<GRID_P, NTHREADS, SMEM_DYN>>>(w1h, w2h, part);

    // 2) reduce partials -> fp16 wsum [k][n]
    reduce_experts_ker<<<(H_DIM * H_DIM / 8) / 256, 256>>>();

    // 3) apply: out = xh @ wsum  (fp32 output)
    appl<<<256, NTHREADS, SMEM_DYN>>>(xh, wsh, (void*)out);
}